// round 1
// baseline (speedup 1.0000x reference)
#include <cuda_runtime.h>
#include <math.h>

#define Bv 64
#define Tv 512
#define Dv 512
#define Uv 1024
#define Gv 4096   // 4*U

// Scratch (static device allocations are the sanctioned scratch mechanism)
__device__ float g_P[(size_t)Tv * Bv * Gv];   // 512 MiB: x-projection [t][b][4U]
__device__ float g_h[2][Bv * Uv];             // double-buffered hidden state
__device__ float g_c[Bv * Uv];                // cell state (block-private per unit)

// ---------------------------------------------------------------------------
// Zero h[0] and c at the start of every replay (determinism across replays).
// ---------------------------------------------------------------------------
__global__ void init_kernel() {
    int i = blockIdx.x * blockDim.x + threadIdx.x;
    if (i < Bv * Uv) {
        g_h[0][i] = 0.0f;
        g_c[i]    = 0.0f;
    }
}

// ---------------------------------------------------------------------------
// x-projection GEMM: P[t*64+b][n] = sum_d x[b][t][d] * Wx[d][n] + bias[n]
// M = T*B = 32768 (m = t*64+b), N = 4096, K = 512.
// Block tile 64x64, BK=16, 256 threads, 4x4 register micro-tile.
// grid: (N/64, M/64)
// ---------------------------------------------------------------------------
__global__ __launch_bounds__(256) void xproj_kernel(
    const float* __restrict__ x,
    const float* __restrict__ Wx,
    const float* __restrict__ bias,
    float* __restrict__ P)
{
    __shared__ float As[16][65];  // [k][m], padded
    __shared__ float Bs[16][64];  // [k][n]

    int tid = threadIdx.x;
    int n0  = blockIdx.x * 64;
    int m0  = blockIdx.y * 64;
    int t   = m0 >> 6;            // all 64 rows of this block share t; b = row

    // A loader: one float4 per thread. a_row = b (0..63), a_c = k-offset {0,4,8,12}
    int a_row = tid >> 2;
    int a_c   = (tid & 3) * 4;
    const float* xrow = x + (size_t)a_row * Tv * Dv + (size_t)t * Dv;

    // B loader: one float4 per thread. b_row = k (0..15), b_c = n-offset
    int b_row = tid >> 4;
    int b_c   = (tid & 15) * 4;

    int tx = tid & 15;            // col group (0..15)
    int ty = tid >> 4;            // row group (0..15)

    float acc[4][4];
#pragma unroll
    for (int i = 0; i < 4; i++)
#pragma unroll
        for (int j = 0; j < 4; j++) acc[i][j] = 0.0f;

    for (int kc = 0; kc < Dv; kc += 16) {
        float4 av = *(const float4*)(xrow + kc + a_c);
        As[a_c + 0][a_row] = av.x;
        As[a_c + 1][a_row] = av.y;
        As[a_c + 2][a_row] = av.z;
        As[a_c + 3][a_row] = av.w;
        float4 bv = *(const float4*)(Wx + (size_t)(kc + b_row) * Gv + n0 + b_c);
        *(float4*)&Bs[b_row][b_c] = bv;
        __syncthreads();

#pragma unroll
        for (int k = 0; k < 16; k++) {
            float a0 = As[k][ty * 4 + 0];
            float a1 = As[k][ty * 4 + 1];
            float a2 = As[k][ty * 4 + 2];
            float a3 = As[k][ty * 4 + 3];
            float4 b4 = *(const float4*)&Bs[k][tx * 4];
            acc[0][0] += a0 * b4.x; acc[0][1] += a0 * b4.y; acc[0][2] += a0 * b4.z; acc[0][3] += a0 * b4.w;
            acc[1][0] += a1 * b4.x; acc[1][1] += a1 * b4.y; acc[1][2] += a1 * b4.z; acc[1][3] += a1 * b4.w;
            acc[2][0] += a2 * b4.x; acc[2][1] += a2 * b4.y; acc[2][2] += a2 * b4.z; acc[2][3] += a2 * b4.w;
            acc[3][0] += a3 * b4.x; acc[3][1] += a3 * b4.y; acc[3][2] += a3 * b4.z; acc[3][3] += a3 * b4.w;
        }
        __syncthreads();
    }

    float4 bb = *(const float4*)(bias + n0 + tx * 4);
#pragma unroll
    for (int i = 0; i < 4; i++) {
        float4 o;
        o.x = acc[i][0] + bb.x;
        o.y = acc[i][1] + bb.y;
        o.z = acc[i][2] + bb.z;
        o.w = acc[i][3] + bb.w;
        *(float4*)(P + (size_t)(m0 + ty * 4 + i) * Gv + n0 + tx * 4) = o;
    }
}

// ---------------------------------------------------------------------------
// One LSTM timestep. grid = 128 blocks, 128 threads (4 warps).
// Block bu owns hidden units [bu*8, bu*8+8) -> 32 gate columns
// n(lc) = (lc/8)*1024 + u_base + (lc%8), lc in [0,32).
// GEMM: gates[64][32] = h @ Wh[:, cols], K=1024 in chunks of 64.
// Then fused LSTM pointwise update for the owned units.
// ---------------------------------------------------------------------------
__global__ __launch_bounds__(128) void step_kernel(
    const float* __restrict__ Wh,
    float* __restrict__ out,
    int t)
{
    __shared__ float hs[64][68];   // h chunk [b][kk], padded
    __shared__ float ws[64][32];   // Wh chunk [kk][lc]
    __shared__ float gs[64][33];   // raw gates [b][lc], padded

    int tid    = threadIdx.x;
    int warp   = tid >> 5;
    int lane   = tid & 31;
    int u_base = blockIdx.x * 8;

    const float* hin  = g_h[t & 1];
    float*       hout = g_h[(t + 1) & 1];

    // micro-tile: rows r0..r0+3, cols c0..c0+3
    int rg = lane >> 3;            // 0..3
    int cg = lane & 7;             // 0..7
    int r0 = warp * 16 + rg * 4;   // 0..60
    int c0 = cg * 4;               // 0..28

    float acc[4][4];
#pragma unroll
    for (int i = 0; i < 4; i++)
#pragma unroll
        for (int j = 0; j < 4; j++) acc[i][j] = 0.0f;

    for (int kc = 0; kc < Uv; kc += 64) {
        // stage h chunk: 64 x 64 floats = 1024 float4, 8 per thread
#pragma unroll
        for (int i = 0; i < 8; i++) {
            int idx = tid + i * 128;       // 0..1023
            int b   = idx >> 4;            // 16 float4 per row
            int k4  = (idx & 15) * 4;
            float4 v = *(const float4*)(hin + b * Uv + kc + k4);
            *(float4*)&hs[b][k4] = v;
        }
        // stage Wh chunk: 64 x 32 floats = 512 float4, 4 per thread
#pragma unroll
        for (int i = 0; i < 4; i++) {
            int idx = tid + i * 128;       // 0..511
            int kk  = idx >> 3;            // 8 float4 per kk-row
            int q   = idx & 7;             // gate = q>>1, half = q&1
            int n   = (q >> 1) * Uv + u_base + (q & 1) * 4;
            float4 v = *(const float4*)(Wh + (size_t)(kc + kk) * Gv + n);
            *(float4*)&ws[kk][q * 4] = v;
        }
        __syncthreads();

#pragma unroll 8
        for (int kk = 0; kk < 64; kk++) {
            float4 wv = *(const float4*)&ws[kk][c0];
            float h0 = hs[r0 + 0][kk];
            float h1 = hs[r0 + 1][kk];
            float h2 = hs[r0 + 2][kk];
            float h3 = hs[r0 + 3][kk];
            acc[0][0] += h0 * wv.x; acc[0][1] += h0 * wv.y; acc[0][2] += h0 * wv.z; acc[0][3] += h0 * wv.w;
            acc[1][0] += h1 * wv.x; acc[1][1] += h1 * wv.y; acc[1][2] += h1 * wv.z; acc[1][3] += h1 * wv.w;
            acc[2][0] += h2 * wv.x; acc[2][1] += h2 * wv.y; acc[2][2] += h2 * wv.z; acc[2][3] += h2 * wv.w;
            acc[3][0] += h3 * wv.x; acc[3][1] += h3 * wv.y; acc[3][2] += h3 * wv.z; acc[3][3] += h3 * wv.w;
        }
        __syncthreads();
    }

    // park raw gates in SMEM so each (b, unit) pair can gather its 4 gates
#pragma unroll
    for (int i = 0; i < 4; i++)
#pragma unroll
        for (int j = 0; j < 4; j++)
            gs[r0 + i][c0 + j] = acc[i][j];
    __syncthreads();

    // pointwise LSTM cell: 64 batches x 8 units = 512 pairs, 4 per thread
    const float* Pt = g_P + (size_t)t * Bv * Gv;
#pragma unroll
    for (int p = tid; p < 512; p += 128) {
        int b = p >> 3;
        int j = p & 7;
        int u = u_base + j;
        const float* Pb = Pt + (size_t)b * Gv;

        float xi = gs[b][j]      + Pb[u];
        float xf = gs[b][8 + j]  + Pb[Uv + u];
        float xg = gs[b][16 + j] + Pb[2 * Uv + u];
        float xo = gs[b][24 + j] + Pb[3 * Uv + u];

        float ig = 1.0f / (1.0f + expf(-xi));
        float fg = 1.0f / (1.0f + expf(-xf));
        float gg = tanhf(xg);
        float og = 1.0f / (1.0f + expf(-xo));

        int idx = b * Uv + u;
        float c = fg * g_c[idx] + ig * gg;
        g_c[idx] = c;
        float h = og * tanhf(c);
        hout[idx] = h;
        out[((size_t)b * Tv + t) * Uv + u] = h;
    }
}

// ---------------------------------------------------------------------------
// Launch: init -> xproj -> 512 sequential step kernels. All graph-capturable.
// ---------------------------------------------------------------------------
extern "C" void kernel_launch(void* const* d_in, const int* in_sizes, int n_in,
                              void* d_out, int out_size)
{
    const float* x    = (const float*)d_in[0];   // [64, 512, 512]
    const float* Wx   = (const float*)d_in[1];   // [512, 4096]
    const float* Wh   = (const float*)d_in[2];   // [1024, 4096]
    const float* bias = (const float*)d_in[3];   // [4096]
    float* out = (float*)d_out;                  // [64, 512, 1024]

    float* P;
    cudaGetSymbolAddress((void**)&P, g_P);

    init_kernel<<<(Bv * Uv + 255) / 256, 256>>>();

    dim3 xgrid(Gv / 64, (Tv * Bv) / 64);
    xproj_kernel<<<xgrid, 256>>>(x, Wx, bias, P);

    for (int t = 0; t < Tv; t++) {
        step_kernel<<<128, 128>>>(Wh, out, t);
    }
}